// round 14
// baseline (speedup 1.0000x reference)
#include <cuda_runtime.h>
#include <cuda_bf16.h>

#define NCLS   1000
#define NCLS4  250          // NCLS / 4 float4 per row

// Scratch (no device allocation allowed -> __device__ globals)
// Fixed-point Q32 accumulators: integer atomics commute -> bit-deterministic.
__device__ unsigned long long g_lsum = 0;   // sum(loss) * 2^32
__device__ unsigned int       g_cnt  = 0;   // valid-token count
__device__ unsigned int       g_ctr  = 0;   // finished-block ticket

// Fire-and-forget reductions (no return value -> no latency wait)
__device__ __forceinline__ void red_add_u64(unsigned long long* p, unsigned long long v)
{
    asm volatile("red.relaxed.gpu.global.add.u64 [%0], %1;" :: "l"(p), "l"(v) : "memory");
}
__device__ __forceinline__ void red_add_u32(unsigned int* p, unsigned int v)
{
    asm volatile("red.relaxed.gpu.global.add.u32 [%0], %1;" :: "l"(p), "r"(v) : "memory");
}
// Release prior REDs, acquire for the final reads.
__device__ __forceinline__ unsigned int ticket_acq_rel(unsigned int* p)
{
    unsigned int old;
    asm volatile("atom.acq_rel.gpu.global.add.u32 %0, [%1], 1;"
                 : "=r"(old) : "l"(p) : "memory");
    return old;
}
__device__ __forceinline__ unsigned long long ld_acq_u64(const unsigned long long* p)
{
    unsigned long long v;
    asm volatile("ld.acquire.gpu.global.u64 %0, [%1];" : "=l"(v) : "l"(p) : "memory");
    return v;
}
__device__ __forceinline__ unsigned int ld_acq_u32(const unsigned int* p)
{
    unsigned int v;
    asm volatile("ld.acquire.gpu.global.u32 %0, [%1];" : "=r"(v) : "l"(p) : "memory");
    return v;
}

// ---------------------------------------------------------------------------
// Single fused kernel, 1 token/warp, grid 4096.
// s3 (row sum) and s2 (100-block sum) are both computed IN the streaming pass
// (s2 via one predicated add per float4 — the 100-block is float4-aligned).
// Only the 10-float s1 strip is re-read; s0 comes from it via shuffle.
// Epilogue: thread 0 fires 2 non-returning REDs + 1 ticket (no block wait);
// the globally-last thread finalizes the scalar and resets state.
// ---------------------------------------------------------------------------
__global__ __launch_bounds__(256) void hll_fused(
    const float* __restrict__ inputs,
    const int*   __restrict__ target,   // int32 (JAX downcasts int64 w/o x64)
    float* __restrict__ out,
    int N, int nblk)
{
    const int warp = threadIdx.x >> 5;
    const int lane = threadIdx.x & 31;
    const int n = (blockIdx.x << 3) + warp;

    float lsum = 0.f, csum = 0.f;

    if (n < N) {
        const int ti = target[n];
        const bool valid = (ti != -100);
        const int t   = valid ? ti : 0;
        const int lo1 = (t / 10)  * 10;         // start of 10-block
        const int f0  = ((t / 100) * 100) >> 2; // first float4 of 100-block (=25k)

        const float*  __restrict__ rowf = inputs + (size_t)n * NCLS;
        const float4* __restrict__ row  = reinterpret_cast<const float4*>(rowf);

        // ---- Streaming pass: s3 (all) + s2 (100-block, float4-aligned) ----
        float a0 = 0.f, a1 = 0.f, a2 = 0.f, a3 = 0.f;
        float s2 = 0.f;
        #pragma unroll
        for (int it = 0; it < 8; ++it) {
            const int idx = lane + (it << 5);
            if (idx < NCLS4) {
                const float4 v = row[idx];
                a0 += v.x; a1 += v.y; a2 += v.z; a3 += v.w;
                const float q = (v.x + v.y) + (v.z + v.w);
                if ((unsigned)(idx - f0) < 25u) s2 += q;
            }
        }
        float s3 = (a0 + a1) + (a2 + a3);

        // ---- Tiny re-read: 10-float s1 strip; s0 via shuffle from it ----
        const float s1v = (lane < 10) ? rowf[lo1 + lane] : 0.f;
        const float s0  = __shfl_sync(0xffffffffu, s1v, t - lo1);
        float s1 = s1v;

        // ---- Warp butterfly reduce s1,s2,s3 ----
        #pragma unroll
        for (int off = 16; off; off >>= 1) {
            s1 += __shfl_xor_sync(0xffffffffu, s1, off);
            s2 += __shfl_xor_sync(0xffffffffu, s2, off);
            s3 += __shfl_xor_sync(0xffffffffu, s3, off);
        }

        if (lane == 0 && valid) {
            const float u0 = (s0 != 0.f) ? -logf(s0 / s1) : 0.f;
            const float u1 = (s1 != 0.f) ? -logf(s1 / s2) : 0.f;
            const float u2 = (s2 != 0.f) ? -logf(s2 / s3) : 0.f;
            lsum = u0 + 0.60653065971263342f * u1   // exp(-0.5)
                      + 0.36787944117144233f * u2;  // exp(-1.0)
            csum = 1.f;
        }
    }

    // ---- Per-block combine (one syncthreads; no post-atomic wait) ----
    __shared__ float2 sacc[8];
    if (lane == 0) sacc[warp] = make_float2(lsum, csum);
    __syncthreads();

    if (threadIdx.x == 0) {
        float L = 0.f, C = 0.f;
        #pragma unroll
        for (int w = 0; w < 8; ++w) { L += sacc[w].x; C += sacc[w].y; }

        // Exact fixed-point conversion: L has 24-bit mantissa, L*2^32 < 2^53.
        const unsigned long long fx =
            (unsigned long long)__double2ll_rn((double)L * 4294967296.0);
        red_add_u64(&g_lsum, fx);                 // fire-and-forget
        red_add_u32(&g_cnt, (unsigned int)C);     // fire-and-forget

        const unsigned int ticket = ticket_acq_rel(&g_ctr);
        if (ticket == (unsigned)(nblk - 1)) {
            // Globally last thread: all REDs are release-ordered before their
            // tickets -> visible now. Finalize + reset for next graph replay.
            const unsigned long long ls = ld_acq_u64(&g_lsum);
            const unsigned int       cn = ld_acq_u32(&g_cnt);
            const double Lsum = (double)(long long)ls * (1.0 / 4294967296.0);
            const double cnt  = (cn > 0u) ? (double)cn : 1.0;
            out[0] = (float)(Lsum / cnt);
            g_lsum = 0ull;
            g_cnt  = 0u;
            g_ctr  = 0u;
        }
    }
}

// ---------------------------------------------------------------------------
// Inputs (metadata order): inputs f32 [N,1000], target i32 [N],
//                          onehot_num, onehot_den, weights (unused)
// ---------------------------------------------------------------------------
extern "C" void kernel_launch(void* const* d_in, const int* in_sizes, int n_in,
                              void* d_out, int out_size)
{
    const float* inputs = (const float*)d_in[0];
    const int*   target = (const int*)d_in[1];
    float*       out    = (float*)d_out;

    const int N = in_sizes[1];
    const int nblk = (N + 7) / 8;            // 4096 for N=32768 (1 tok/warp)

    hll_fused<<<nblk, 256>>>(inputs, target, out, N, nblk);
}